// round 14
// baseline (speedup 1.0000x reference)
#include <cuda_runtime.h>
#include <cuda_bf16.h>
#include <stdint.h>

#define B_   8
#define T_   2048
#define D_   1024
#define KQ_  128
#define TOPK 8
#define LK   8              // per-lane top-8 in simc (containment guarantee)
#define NC   64             // candidates per row
#define BT_  (B_ * T_)

#define GATH_N ((size_t)BT_ * TOPK * D_)   // 134217728
#define IDX_N  ((size_t)BT_ * TOPK)        // 131072

// Scratch (__device__ globals; allocation-free rule)
__device__ float    g_q[BT_ * KQ_];
__device__ float    g_k[BT_ * KQ_];
__device__ uint32_t g_qh[BT_ * (KQ_ / 2)];   // bf16 h-plane
__device__ uint32_t g_kh[BT_ * (KQ_ / 2)];
__device__ int      g_idx[BT_ * TOPK];
__device__ int      g_cand[BT_ * NC];

__device__ __forceinline__ uint32_t bfpair(float a, float b) {
    __nv_bfloat162 t = __floats2bfloat162_rn(a, b);
    return *reinterpret_cast<uint32_t*>(&t);
}

#define MMA(cc, aa, bb)                                                         \
    asm volatile("mma.sync.aligned.m16n8k16.row.col.f32.bf16.bf16.f32 "        \
                 "{%0,%1,%2,%3},{%4,%5,%6,%7},{%8,%9},{%0,%1,%2,%3};"          \
                 : "+f"((cc)[0]), "+f"((cc)[1]), "+f"((cc)[2]), "+f"((cc)[3])  \
                 : "r"((aa)[0]), "r"((aa)[1]), "r"((aa)[2]), "r"((aa)[3]),     \
                   "r"((bb)[0]), "r"((bb)[1]))

// ---------------------------------------------------------------------------
// Kernel A: proj — R1's kernel verbatim (bit-identical q/k; known-good draw),
// plus bf16 h-plane emission in the epilogue.
// ---------------------------------------------------------------------------
__global__ __launch_bounds__(256) void proj_kernel(
    const float* __restrict__ x,
    const float* __restrict__ Wq, const float* __restrict__ bq,
    const float* __restrict__ Wk, const float* __restrict__ bk)
{
    __shared__ float As[32][68];
    __shared__ float Bs[32][260];

    const int tid = threadIdx.x;
    const int m0  = blockIdx.x * 64;
    const int ty  = tid >> 5;
    const int tx  = tid & 31;

    float acc[8][8];
#pragma unroll
    for (int i = 0; i < 8; i++)
#pragma unroll
        for (int j = 0; j < 8; j++) acc[i][j] = 0.f;

    for (int k0 = 0; k0 < D_; k0 += 32) {
#pragma unroll
        for (int l = 0; l < 2; l++) {
            int e  = tid + l * 256;
            int r  = e >> 3;
            int c4 = e & 7;
            float4 v = *reinterpret_cast<const float4*>(
                &x[(size_t)(m0 + r) * D_ + k0 + c4 * 4]);
            As[c4 * 4 + 0][r] = v.x;
            As[c4 * 4 + 1][r] = v.y;
            As[c4 * 4 + 2][r] = v.z;
            As[c4 * 4 + 3][r] = v.w;
        }
#pragma unroll
        for (int l = 0; l < 8; l++) {
            int e  = tid + l * 256;
            int n  = e >> 3;
            int c4 = e & 7;
            const float* Wsrc = (n < 128) ? &Wq[(size_t)n * D_]
                                          : &Wk[(size_t)(n - 128) * D_];
            float4 v = *reinterpret_cast<const float4*>(&Wsrc[k0 + c4 * 4]);
            Bs[c4 * 4 + 0][n] = v.x;
            Bs[c4 * 4 + 1][n] = v.y;
            Bs[c4 * 4 + 2][n] = v.z;
            Bs[c4 * 4 + 3][n] = v.w;
        }
        __syncthreads();

#pragma unroll 4
        for (int d = 0; d < 32; d++) {
            float4 a0 = *reinterpret_cast<const float4*>(&As[d][ty * 8]);
            float4 a1 = *reinterpret_cast<const float4*>(&As[d][ty * 8 + 4]);
            float4 b0 = *reinterpret_cast<const float4*>(&Bs[d][tx * 8]);
            float4 b1 = *reinterpret_cast<const float4*>(&Bs[d][tx * 8 + 4]);
            float a[8] = {a0.x, a0.y, a0.z, a0.w, a1.x, a1.y, a1.z, a1.w};
            float b[8] = {b0.x, b0.y, b0.z, b0.w, b1.x, b1.y, b1.z, b1.w};
#pragma unroll
            for (int i = 0; i < 8; i++)
#pragma unroll
                for (int j = 0; j < 8; j++) acc[i][j] += a[i] * b[j];
        }
        __syncthreads();
    }

    float* dst;
    uint32_t* hdst;
    const float* bias;
    int n0;
    if (tx < 16) { dst = g_q; hdst = g_qh; bias = bq; n0 = tx * 8; }
    else         { dst = g_k; hdst = g_kh; bias = bk; n0 = (tx - 16) * 8; }
    float bb[8];
#pragma unroll
    for (int j = 0; j < 8; j++) bb[j] = bias[n0 + j];

#pragma unroll
    for (int i = 0; i < 8; i++) {
        int m = m0 + ty * 8 + i;
        float4 v0 = make_float4(acc[i][0] + bb[0], acc[i][1] + bb[1],
                                acc[i][2] + bb[2], acc[i][3] + bb[3]);
        float4 v1 = make_float4(acc[i][4] + bb[4], acc[i][5] + bb[5],
                                acc[i][6] + bb[6], acc[i][7] + bb[7]);
        *reinterpret_cast<float4*>(&dst[(size_t)m * KQ_ + n0])     = v0;
        *reinterpret_cast<float4*>(&dst[(size_t)m * KQ_ + n0 + 4]) = v1;
        uint4 hv = make_uint4(bfpair(v0.x, v0.y), bfpair(v0.z, v0.w),
                              bfpair(v1.x, v1.y), bfpair(v1.z, v1.w));
        *reinterpret_cast<uint4*>(&hdst[(size_t)m * 64 + (n0 >> 1)]) = hv;
    }
}

// ---------------------------------------------------------------------------
// Kernel B: candidate pass (R10 version verbatim: plain loads, 2 CTA/SM).
// Idempotent: relaunching rewrites identical g_cand values.
// ---------------------------------------------------------------------------
#define QST 68
#define TPL (128 * QST)                  // 8704 u32 per tile plane
#define SIM_SMEM (2 * TPL * 4)           // 69632 B

__global__ __launch_bounds__(256, 2) void simc_kernel()
{
    extern __shared__ uint32_t sm[];
    uint32_t* Qp = sm;
    uint32_t* Kp = sm + TPL;

    const int tid  = threadIdx.x;
    const int lane = tid & 31;
    const int grp  = lane >> 2, tig = lane & 3;
    const int w    = tid >> 5;
    const int b    = blockIdx.y;
    const int t0   = blockIdx.x * 128;
    const int half = blockIdx.z;

    {
        const uint4* src = reinterpret_cast<const uint4*>(
            &g_qh[((size_t)b * T_ + t0) * 64]);
#pragma unroll
        for (int l = 0; l < 8; l++) {
            int e = tid + l * 256;
            int row = e >> 4, c8 = e & 15;
            *reinterpret_cast<uint4*>(&Qp[row * QST + c8 * 4]) = src[e];
        }
    }

    float tv0[LK], tv1[LK];
    int   ti0[LK], ti1[LK];
#pragma unroll
    for (int j = 0; j < LK; j++) {
        tv0[j] = -3.402823466e38f; ti0[j] = 0x7FFFFFFF;
        tv1[j] = -3.402823466e38f; ti1[j] = 0x7FFFFFFF;
    }

    const int rbA = (16 * w + grp) * QST;

    for (int st = 0; st < 8; st++) {
        const int s0 = half * 1024 + st * 128;
        {
            const uint4* src = reinterpret_cast<const uint4*>(
                &g_kh[((size_t)b * T_ + s0) * 64]);
#pragma unroll
            for (int l = 0; l < 8; l++) {
                int e = tid + l * 256;
                int row = e >> 4, c8 = e & 15;
                *reinterpret_cast<uint4*>(&Kp[row * QST + c8 * 4]) = src[e];
            }
        }
        __syncthreads();

        float c[16][4];
#pragma unroll
        for (int nt = 0; nt < 16; nt++)
#pragma unroll
            for (int e = 0; e < 4; e++) c[nt][e] = 0.f;

#pragma unroll
        for (int kk = 0; kk < 8; kk++) {
            uint32_t a[4];
            int ra = rbA + kk * 8 + tig;
            a[0] = Qp[ra];
            a[1] = Qp[ra + 8 * QST];
            a[2] = Qp[ra + 4];
            a[3] = Qp[ra + 8 * QST + 4];
#pragma unroll
            for (int nt = 0; nt < 16; nt++) {
                uint32_t bf[2];
                int rb = (nt * 8 + grp) * QST + kk * 8 + tig;
                bf[0] = Kp[rb];
                bf[1] = Kp[rb + 4];
                MMA(c[nt], a, bf);
            }
        }

#pragma unroll
        for (int nt = 0; nt < 16; nt++) {
            int sb = s0 + nt * 8 + 2 * tig;
#pragma unroll
            for (int e = 0; e < 2; e++) {
                float v = c[nt][e];
                if (v > tv0[LK - 1]) {
                    tv0[LK-1] = v; ti0[LK-1] = sb + e;
#pragma unroll
                    for (int p = LK-1; p > 0; p--)
                        if (tv0[p] > tv0[p-1]) {
                            float a_ = tv0[p]; tv0[p] = tv0[p-1]; tv0[p-1] = a_;
                            int   c_ = ti0[p]; ti0[p] = ti0[p-1]; ti0[p-1] = c_;
                        }
                }
            }
#pragma unroll
            for (int e = 0; e < 2; e++) {
                float v = c[nt][2 + e];
                if (v > tv1[LK - 1]) {
                    tv1[LK-1] = v; ti1[LK-1] = sb + e;
#pragma unroll
                    for (int p = LK-1; p > 0; p--)
                        if (tv1[p] > tv1[p-1]) {
                            float a_ = tv1[p]; tv1[p] = tv1[p-1]; tv1[p-1] = a_;
                            int   c_ = ti1[p]; ti1[p] = ti1[p-1]; ti1[p-1] = c_;
                        }
                }
            }
        }
        __syncthreads();
    }

    {
        size_t r0 = (size_t)b * T_ + t0 + 16 * w + grp;
        size_t r1 = r0 + 8;
        int base = half * 32 + tig * 8;
#pragma unroll
        for (int j = 0; j < LK; j++) {
            g_cand[r0 * NC + base + j] = ti0[j];
            g_cand[r1 * NC + base + j] = ti1[j];
        }
    }
}

// ---------------------------------------------------------------------------
// Kernel R: rescore (R13 version).  Idempotent: rewrites identical outputs.
// ---------------------------------------------------------------------------
__global__ __launch_bounds__(256) void rescore_kernel(float* __restrict__ out)
{
    const int tid  = threadIdx.x;
    const int w    = tid >> 5, lane = tid & 31;
    const int row  = blockIdx.x * 8 + w;
    const int b    = row >> 11;

    __shared__ float4 qs[8][32];

    qs[w][lane] = reinterpret_cast<const float4*>(&g_q[(size_t)row * KQ_])[lane];
    __syncwarp();

    int i0 = g_cand[(size_t)row * NC + lane];
    int i1 = g_cand[(size_t)row * NC + 32 + lane];
    const float4* k0 = reinterpret_cast<const float4*>(
        &g_k[((size_t)(b << 11) + i0) * KQ_]);
    const float4* k1 = reinterpret_cast<const float4*>(
        &g_k[((size_t)(b << 11) + i1) * KQ_]);
    float v0 = 0.f, v1 = 0.f;
#pragma unroll
    for (int d4 = 0; d4 < 32; d4++) {
        float4 qv = qs[w][d4];
        float4 kv0 = k0[d4];
        float4 kv1 = k1[d4];
        v0 = fmaf(qv.x, kv0.x, v0); v0 = fmaf(qv.y, kv0.y, v0);
        v0 = fmaf(qv.z, kv0.z, v0); v0 = fmaf(qv.w, kv0.w, v0);
        v1 = fmaf(qv.x, kv1.x, v1); v1 = fmaf(qv.y, kv1.y, v1);
        v1 = fmaf(qv.z, kv1.z, v1); v1 = fmaf(qv.w, kv1.w, v1);
    }

    const float NEG = -3.402823466e38f;
    const float scale = 0.08838834764831843f;   // 1/sqrt(128)
    float* out_idx = out + GATH_N;
    float* out_sim = out + GATH_N + IDX_N;

#pragma unroll
    for (int j = 0; j < TOPK; j++) {
        float bv; int bi;
        bool first = (v0 > v1) || (v0 == v1 && i0 < i1);
        bv = first ? v0 : v1;
        bi = first ? i0 : i1;
#pragma unroll
        for (int off = 16; off > 0; off >>= 1) {
            float ov = __shfl_xor_sync(0xFFFFFFFFu, bv, off);
            int   oi = __shfl_xor_sync(0xFFFFFFFFu, bi, off);
            if (ov > bv || (ov == bv && oi < bi)) { bv = ov; bi = oi; }
        }
        if (i0 == bi) v0 = NEG;
        if (i1 == bi) v1 = NEG;
        if (lane == 0) {
            g_idx[(size_t)row * TOPK + j]   = bi;
            out_idx[(size_t)row * TOPK + j] = (float)bi;
            out_sim[(size_t)row * TOPK + j] = bv * scale;
        }
    }
}

// ---------------------------------------------------------------------------
// Kernel C: gather.  Block per (b,t); streaming stores.
// ---------------------------------------------------------------------------
__global__ __launch_bounds__(256) void gather_kernel(
    const float* __restrict__ x, float* __restrict__ out)
{
    int bt = blockIdx.x;
    int b  = bt >> 11;
    const float4* xb = reinterpret_cast<const float4*>(x) + (size_t)(b << 11) * 256;
    float4* dst = reinterpret_cast<float4*>(out) + (size_t)bt * TOPK * 256;
#pragma unroll
    for (int j = 0; j < TOPK; j++) {
        int src_t = g_idx[bt * TOPK + j];
        float4 v = __ldg(&xb[(size_t)src_t * 256 + threadIdx.x]);
        __stcs(&dst[(size_t)j * 256 + threadIdx.x], v);
    }
}

// ---------------------------------------------------------------------------
// ATTRIBUTION ROUND: simc launched 3x, rescore 2x (both idempotent).
//   dur - 550.7 = 2*simc + rescore  -> solves the per-kernel split.
// ---------------------------------------------------------------------------
extern "C" void kernel_launch(void* const* d_in, const int* in_sizes, int n_in,
                              void* d_out, int out_size)
{
    const float* x  = (const float*)d_in[0];
    const float* Wq = (const float*)d_in[1];
    const float* bq = (const float*)d_in[2];
    const float* Wk = (const float*)d_in[3];
    const float* bk = (const float*)d_in[4];
    float* out = (float*)d_out;

    cudaFuncSetAttribute(simc_kernel,
                         cudaFuncAttributeMaxDynamicSharedMemorySize, SIM_SMEM);

    proj_kernel<<<BT_ / 64, 256>>>(x, Wq, bq, Wk, bk);

    dim3 gridB(T_ / 128, B_, 2);
    simc_kernel<<<gridB, 256, SIM_SMEM>>>();
    simc_kernel<<<gridB, 256, SIM_SMEM>>>();   // attribution duplicate 1
    simc_kernel<<<gridB, 256, SIM_SMEM>>>();   // attribution duplicate 2

    rescore_kernel<<<BT_ / 8, 256>>>(out);
    rescore_kernel<<<BT_ / 8, 256>>>(out);     // attribution duplicate

    gather_kernel<<<BT_, 256>>>(x, out);
}

// round 15
// speedup vs baseline: 1.8173x; 1.8173x over previous
#include <cuda_runtime.h>
#include <cuda_bf16.h>
#include <stdint.h>

#define B_   8
#define T_   2048
#define D_   1024
#define KQ_  128
#define TOPK 8
#define LK   8              // per-lane top-8 in simc (containment guarantee)
#define NC   64             // candidates per row
#define NF   16             // candidates exactly rescored
#define BT_  (B_ * T_)

#define GATH_N ((size_t)BT_ * TOPK * D_)   // 134217728
#define IDX_N  ((size_t)BT_ * TOPK)        // 131072

// Scratch (__device__ globals; allocation-free rule)
__device__ float    g_q[BT_ * KQ_];
__device__ float    g_k[BT_ * KQ_];
__device__ uint32_t g_qh[BT_ * (KQ_ / 2)];   // bf16 h-plane
__device__ uint32_t g_kh[BT_ * (KQ_ / 2)];
__device__ int      g_idx[BT_ * TOPK];
__device__ int      g_cand[BT_ * NC];
__device__ float    g_cval[BT_ * NC];

__device__ __forceinline__ uint32_t bfpair(float a, float b) {
    __nv_bfloat162 t = __floats2bfloat162_rn(a, b);
    return *reinterpret_cast<uint32_t*>(&t);
}

#define MMA(cc, aa, bb)                                                         \
    asm volatile("mma.sync.aligned.m16n8k16.row.col.f32.bf16.bf16.f32 "        \
                 "{%0,%1,%2,%3},{%4,%5,%6,%7},{%8,%9},{%0,%1,%2,%3};"          \
                 : "+f"((cc)[0]), "+f"((cc)[1]), "+f"((cc)[2]), "+f"((cc)[3])  \
                 : "r"((aa)[0]), "r"((aa)[1]), "r"((aa)[2]), "r"((aa)[3]),     \
                   "r"((bb)[0]), "r"((bb)[1]))

// ---------------------------------------------------------------------------
// Kernel A: proj — R1's kernel verbatim (bit-identical q/k; known-good draw),
// plus bf16 h-plane emission in the epilogue.
// ---------------------------------------------------------------------------
__global__ __launch_bounds__(256) void proj_kernel(
    const float* __restrict__ x,
    const float* __restrict__ Wq, const float* __restrict__ bq,
    const float* __restrict__ Wk, const float* __restrict__ bk)
{
    __shared__ float As[32][68];
    __shared__ float Bs[32][260];

    const int tid = threadIdx.x;
    const int m0  = blockIdx.x * 64;
    const int ty  = tid >> 5;
    const int tx  = tid & 31;

    float acc[8][8];
#pragma unroll
    for (int i = 0; i < 8; i++)
#pragma unroll
        for (int j = 0; j < 8; j++) acc[i][j] = 0.f;

    for (int k0 = 0; k0 < D_; k0 += 32) {
#pragma unroll
        for (int l = 0; l < 2; l++) {
            int e  = tid + l * 256;
            int r  = e >> 3;
            int c4 = e & 7;
            float4 v = *reinterpret_cast<const float4*>(
                &x[(size_t)(m0 + r) * D_ + k0 + c4 * 4]);
            As[c4 * 4 + 0][r] = v.x;
            As[c4 * 4 + 1][r] = v.y;
            As[c4 * 4 + 2][r] = v.z;
            As[c4 * 4 + 3][r] = v.w;
        }
#pragma unroll
        for (int l = 0; l < 8; l++) {
            int e  = tid + l * 256;
            int n  = e >> 3;
            int c4 = e & 7;
            const float* Wsrc = (n < 128) ? &Wq[(size_t)n * D_]
                                          : &Wk[(size_t)(n - 128) * D_];
            float4 v = *reinterpret_cast<const float4*>(&Wsrc[k0 + c4 * 4]);
            Bs[c4 * 4 + 0][n] = v.x;
            Bs[c4 * 4 + 1][n] = v.y;
            Bs[c4 * 4 + 2][n] = v.z;
            Bs[c4 * 4 + 3][n] = v.w;
        }
        __syncthreads();

#pragma unroll 4
        for (int d = 0; d < 32; d++) {
            float4 a0 = *reinterpret_cast<const float4*>(&As[d][ty * 8]);
            float4 a1 = *reinterpret_cast<const float4*>(&As[d][ty * 8 + 4]);
            float4 b0 = *reinterpret_cast<const float4*>(&Bs[d][tx * 8]);
            float4 b1 = *reinterpret_cast<const float4*>(&Bs[d][tx * 8 + 4]);
            float a[8] = {a0.x, a0.y, a0.z, a0.w, a1.x, a1.y, a1.z, a1.w};
            float b[8] = {b0.x, b0.y, b0.z, b0.w, b1.x, b1.y, b1.z, b1.w};
#pragma unroll
            for (int i = 0; i < 8; i++)
#pragma unroll
                for (int j = 0; j < 8; j++) acc[i][j] += a[i] * b[j];
        }
        __syncthreads();
    }

    float* dst;
    uint32_t* hdst;
    const float* bias;
    int n0;
    if (tx < 16) { dst = g_q; hdst = g_qh; bias = bq; n0 = tx * 8; }
    else         { dst = g_k; hdst = g_kh; bias = bk; n0 = (tx - 16) * 8; }
    float bb[8];
#pragma unroll
    for (int j = 0; j < 8; j++) bb[j] = bias[n0 + j];

#pragma unroll
    for (int i = 0; i < 8; i++) {
        int m = m0 + ty * 8 + i;
        float4 v0 = make_float4(acc[i][0] + bb[0], acc[i][1] + bb[1],
                                acc[i][2] + bb[2], acc[i][3] + bb[3]);
        float4 v1 = make_float4(acc[i][4] + bb[4], acc[i][5] + bb[5],
                                acc[i][6] + bb[6], acc[i][7] + bb[7]);
        *reinterpret_cast<float4*>(&dst[(size_t)m * KQ_ + n0])     = v0;
        *reinterpret_cast<float4*>(&dst[(size_t)m * KQ_ + n0 + 4]) = v1;
        uint4 hv = make_uint4(bfpair(v0.x, v0.y), bfpair(v0.z, v0.w),
                              bfpair(v1.x, v1.y), bfpair(v1.z, v1.w));
        *reinterpret_cast<uint4*>(&hdst[(size_t)m * 64 + (n0 >> 1)]) = hv;
    }
}

// ---------------------------------------------------------------------------
// Kernel B: candidate pass (R10 structure; adds g_cval stores only).
// Grid (16, 8, 2).  Warp w owns rows 16w..16w+15; per-lane per-row top-8.
// ---------------------------------------------------------------------------
#define QST 68
#define TPL (128 * QST)                  // 8704 u32 per tile plane
#define SIM_SMEM (2 * TPL * 4)           // 69632 B

__global__ __launch_bounds__(256, 2) void simc_kernel()
{
    extern __shared__ uint32_t sm[];
    uint32_t* Qp = sm;
    uint32_t* Kp = sm + TPL;

    const int tid  = threadIdx.x;
    const int lane = tid & 31;
    const int grp  = lane >> 2, tig = lane & 3;
    const int w    = tid >> 5;
    const int b    = blockIdx.y;
    const int t0   = blockIdx.x * 128;
    const int half = blockIdx.z;

    {
        const uint4* src = reinterpret_cast<const uint4*>(
            &g_qh[((size_t)b * T_ + t0) * 64]);
#pragma unroll
        for (int l = 0; l < 8; l++) {
            int e = tid + l * 256;
            int row = e >> 4, c8 = e & 15;
            *reinterpret_cast<uint4*>(&Qp[row * QST + c8 * 4]) = src[e];
        }
    }

    float tv0[LK], tv1[LK];
    int   ti0[LK], ti1[LK];
#pragma unroll
    for (int j = 0; j < LK; j++) {
        tv0[j] = -3.402823466e38f; ti0[j] = 0x7FFFFFFF;
        tv1[j] = -3.402823466e38f; ti1[j] = 0x7FFFFFFF;
    }

    const int rbA = (16 * w + grp) * QST;

    for (int st = 0; st < 8; st++) {
        const int s0 = half * 1024 + st * 128;
        {
            const uint4* src = reinterpret_cast<const uint4*>(
                &g_kh[((size_t)b * T_ + s0) * 64]);
#pragma unroll
            for (int l = 0; l < 8; l++) {
                int e = tid + l * 256;
                int row = e >> 4, c8 = e & 15;
                *reinterpret_cast<uint4*>(&Kp[row * QST + c8 * 4]) = src[e];
            }
        }
        __syncthreads();

        float c[16][4];
#pragma unroll
        for (int nt = 0; nt < 16; nt++)
#pragma unroll
            for (int e = 0; e < 4; e++) c[nt][e] = 0.f;

#pragma unroll
        for (int kk = 0; kk < 8; kk++) {
            uint32_t a[4];
            int ra = rbA + kk * 8 + tig;
            a[0] = Qp[ra];
            a[1] = Qp[ra + 8 * QST];
            a[2] = Qp[ra + 4];
            a[3] = Qp[ra + 8 * QST + 4];
#pragma unroll
            for (int nt = 0; nt < 16; nt++) {
                uint32_t bf[2];
                int rb = (nt * 8 + grp) * QST + kk * 8 + tig;
                bf[0] = Kp[rb];
                bf[1] = Kp[rb + 4];
                MMA(c[nt], a, bf);
            }
        }

#pragma unroll
        for (int nt = 0; nt < 16; nt++) {
            int sb = s0 + nt * 8 + 2 * tig;
#pragma unroll
            for (int e = 0; e < 2; e++) {
                float v = c[nt][e];
                if (v > tv0[LK - 1]) {
                    tv0[LK-1] = v; ti0[LK-1] = sb + e;
#pragma unroll
                    for (int p = LK-1; p > 0; p--)
                        if (tv0[p] > tv0[p-1]) {
                            float a_ = tv0[p]; tv0[p] = tv0[p-1]; tv0[p-1] = a_;
                            int   c_ = ti0[p]; ti0[p] = ti0[p-1]; ti0[p-1] = c_;
                        }
                }
            }
#pragma unroll
            for (int e = 0; e < 2; e++) {
                float v = c[nt][2 + e];
                if (v > tv1[LK - 1]) {
                    tv1[LK-1] = v; ti1[LK-1] = sb + e;
#pragma unroll
                    for (int p = LK-1; p > 0; p--)
                        if (tv1[p] > tv1[p-1]) {
                            float a_ = tv1[p]; tv1[p] = tv1[p-1]; tv1[p-1] = a_;
                            int   c_ = ti1[p]; ti1[p] = ti1[p-1]; ti1[p-1] = c_;
                        }
                }
            }
        }
        __syncthreads();
    }

    {
        size_t r0 = (size_t)b * T_ + t0 + 16 * w + grp;
        size_t r1 = r0 + 8;
        int base = half * 32 + tig * 8;
#pragma unroll
        for (int j = 0; j < LK; j++) {
            g_cand[r0 * NC + base + j] = ti0[j];
            g_cval[r0 * NC + base + j] = tv0[j];
            g_cand[r1 * NC + base + j] = ti1[j];
            g_cval[r1 * NC + base + j] = tv1[j];
        }
    }
}

// ---------------------------------------------------------------------------
// Kernel R: rescore, fully warp-parallel.
// (1) NF=16 filter by approx value: 16 shfl-argmax rounds over 64 (2/lane);
// (2) lanes 0-15 exact-rescore one candidate each (R1's verbatim fmaf chain
//     -> bit-identical values);
// (3) 8 shfl-argmax rounds on exact values, comparator (value desc, index
//     asc) == R1 scan-insert semantics.
// All 64 indices per row are distinct (disjoint column buckets), so
// invalidate-by-index is sound.
// ---------------------------------------------------------------------------
__global__ __launch_bounds__(256) void rescore_kernel(float* __restrict__ out)
{
    const int tid  = threadIdx.x;
    const int w    = tid >> 5, lane = tid & 31;
    const int row  = blockIdx.x * 8 + w;
    const int b    = row >> 11;

    __shared__ float4 qs[8][32];

    qs[w][lane] = reinterpret_cast<const float4*>(&g_q[(size_t)row * KQ_])[lane];

    int   i0 = g_cand[(size_t)row * NC + lane];
    int   i1 = g_cand[(size_t)row * NC + 32 + lane];
    float a0 = g_cval[(size_t)row * NC + lane];
    float a1 = g_cval[(size_t)row * NC + 32 + lane];
    __syncwarp();

    const float NEG = -3.402823466e38f;

    // (1) approx-top-16 filter; lane j keeps round-j winner
    int sel = 0x7FFFFFFF;
#pragma unroll
    for (int j = 0; j < NF; j++) {
        float bv; int bi;
        bool first = (a0 > a1) || (a0 == a1 && i0 < i1);
        bv = first ? a0 : a1;
        bi = first ? i0 : i1;
#pragma unroll
        for (int off = 16; off > 0; off >>= 1) {
            float ov = __shfl_xor_sync(0xFFFFFFFFu, bv, off);
            int   oi = __shfl_xor_sync(0xFFFFFFFFu, bi, off);
            if (ov > bv || (ov == bv && oi < bi)) { bv = ov; bi = oi; }
        }
        if (i0 == bi) a0 = NEG;
        if (i1 == bi) a1 = NEG;
        if (lane == j) sel = bi;
    }

    // (2) exact rescore of the 16 selected (R1 FMA order -> bit-identical)
    float ev = NEG;
    int   ei = sel;
    if (lane < NF) {
        const float4* kr = reinterpret_cast<const float4*>(
            &g_k[((size_t)(b << 11) + sel) * KQ_]);
        float acc = 0.f;
#pragma unroll
        for (int d4 = 0; d4 < 32; d4++) {
            float4 qv = qs[w][d4];
            float4 kv = kr[d4];
            acc = fmaf(qv.x, kv.x, acc);
            acc = fmaf(qv.y, kv.y, acc);
            acc = fmaf(qv.z, kv.z, acc);
            acc = fmaf(qv.w, kv.w, acc);
        }
        ev = acc;
    }

    // (3) exact top-8 selection
    const float scale = 0.08838834764831843f;   // 1/sqrt(128)
    float* out_idx = out + GATH_N;
    float* out_sim = out + GATH_N + IDX_N;
#pragma unroll
    for (int j = 0; j < TOPK; j++) {
        float bv = ev; int bi = ei;
#pragma unroll
        for (int off = 16; off > 0; off >>= 1) {
            float ov = __shfl_xor_sync(0xFFFFFFFFu, bv, off);
            int   oi = __shfl_xor_sync(0xFFFFFFFFu, bi, off);
            if (ov > bv || (ov == bv && oi < bi)) { bv = ov; bi = oi; }
        }
        if (ei == bi) ev = NEG;
        if (lane == 0) {
            g_idx[(size_t)row * TOPK + j]   = bi;
            out_idx[(size_t)row * TOPK + j] = (float)bi;
            out_sim[(size_t)row * TOPK + j] = bv * scale;
        }
    }
}

// ---------------------------------------------------------------------------
// Kernel C: gather.  Block per (b,t); streaming stores.
// ---------------------------------------------------------------------------
__global__ __launch_bounds__(256) void gather_kernel(
    const float* __restrict__ x, float* __restrict__ out)
{
    int bt = blockIdx.x;
    int b  = bt >> 11;
    const float4* xb = reinterpret_cast<const float4*>(x) + (size_t)(b << 11) * 256;
    float4* dst = reinterpret_cast<float4*>(out) + (size_t)bt * TOPK * 256;
#pragma unroll
    for (int j = 0; j < TOPK; j++) {
        int src_t = g_idx[bt * TOPK + j];
        float4 v = __ldg(&xb[(size_t)src_t * 256 + threadIdx.x]);
        __stcs(&dst[(size_t)j * 256 + threadIdx.x], v);
    }
}

// ---------------------------------------------------------------------------
extern "C" void kernel_launch(void* const* d_in, const int* in_sizes, int n_in,
                              void* d_out, int out_size)
{
    const float* x  = (const float*)d_in[0];
    const float* Wq = (const float*)d_in[1];
    const float* bq = (const float*)d_in[2];
    const float* Wk = (const float*)d_in[3];
    const float* bk = (const float*)d_in[4];
    float* out = (float*)d_out;

    cudaFuncSetAttribute(simc_kernel,
                         cudaFuncAttributeMaxDynamicSharedMemorySize, SIM_SMEM);

    proj_kernel<<<BT_ / 64, 256>>>(x, Wq, bq, Wk, bk);

    dim3 gridB(T_ / 128, B_, 2);
    simc_kernel<<<gridB, 256, SIM_SMEM>>>();

    rescore_kernel<<<BT_ / 8, 256>>>(out);

    gather_kernel<<<BT_, 256>>>(x, out);
}